// round 1
// baseline (speedup 1.0000x reference)
#include <cuda_runtime.h>
#include <cuda_bf16.h>
#include <cstdint>

// Problem constants (shapes are fixed by the dataset; sizes re-derived defensively)
#define N_NODES 50000
#define N_EDGES 800000
#define N_GRAPHS 64
#define F_IN 6
#define HID 64
#define EMB 128

// ---------------- scratch (static device globals; no allocation) ----------------
__device__ __align__(16) float g_h[(size_t)N_NODES * HID];    // h = x @ W
__device__ __align__(16) float g_x[(size_t)N_NODES * HID];    // aggregated activation
__device__ float g_dinv[N_NODES];
__device__ int   g_deg[N_NODES];
__device__ float g_norm[N_EDGES];
__device__ __align__(16) float g_pool[N_GRAPHS * HID];
__device__ int   g_cnt[N_GRAPHS];

// ---------------- helpers ----------------
__device__ __forceinline__ void red_add_v4(float* p, float4 v) {
    asm volatile("red.global.add.v4.f32 [%0], {%1,%2,%3,%4};"
                 :: "l"(p), "f"(v.x), "f"(v.y), "f"(v.z), "f"(v.w) : "memory");
}

// ---------------- kernels ----------------

// zero deg / pool / cnt
__global__ void k_init(int n) {
    int i = blockIdx.x * blockDim.x + threadIdx.x;
    if (i < n) g_deg[i] = 0;
    if (i < N_GRAPHS * HID) g_pool[i] = 0.f;
    if (i < N_GRAPHS) g_cnt[i] = 0;
}

__global__ void k_count_deg(const int* __restrict__ dst, int nE) {
    int e = blockIdx.x * blockDim.x + threadIdx.x;
    if (e < nE) atomicAdd(&g_deg[dst[e]], 1);
}

__global__ void k_dinv(int n) {
    int i = blockIdx.x * blockDim.x + threadIdx.x;
    if (i < n) g_dinv[i] = rsqrtf((float)g_deg[i] + 1.0f);  // +1 self-loop
}

__global__ void k_norm(const int* __restrict__ src, const int* __restrict__ dst, int nE) {
    int e = blockIdx.x * blockDim.x + threadIdx.x;
    if (e < nE) g_norm[e] = g_dinv[src[e]] * g_dinv[dst[e]];
}

// h = x @ W1  (x: [n,6], W1: [6,64])
__global__ void k_gemm_in6(const float* __restrict__ X, const float* __restrict__ W, int n) {
    int t = blockIdx.x * blockDim.x + threadIdx.x;
    int node = t >> 6, col = t & 63;
    if (node >= n) return;
    const float* xr = X + (size_t)node * F_IN;
    float acc = 0.f;
    #pragma unroll
    for (int k = 0; k < F_IN; k++)
        acc = fmaf(__ldg(xr + k), __ldg(W + k * HID + col), acc);
    g_h[t] = acc;
}

// h = g_x @ W  (g_x: [n,64], W: [64,64]); W staged in shared, 4 nodes per 256-thr block
__global__ void k_gemm64(const float* __restrict__ W, int n) {
    __shared__ float Ws[HID][HID + 1];
    int tid = threadIdx.x;
    for (int i = tid; i < HID * HID; i += 256)
        Ws[i >> 6][i & 63] = W[i];
    __syncthreads();
    int node = blockIdx.x * 4 + (tid >> 6);
    int col = tid & 63;
    if (node >= n) return;
    const float* xr = g_x + (size_t)node * HID;
    float acc = 0.f;
    #pragma unroll
    for (int k = 0; k < HID; k++)
        acc = fmaf(__ldg(xr + k), Ws[k][col], acc);
    g_h[(size_t)node * HID + col] = acc;
}

__global__ void k_zero(float* __restrict__ p, int n) {
    int i = blockIdx.x * blockDim.x + threadIdx.x;
    if (i < n) p[i] = 0.f;
}

// scatter: out[dst] += h[src] * norm[e]; 16 threads per edge (float4 chunks)
__global__ void k_scatter(const int* __restrict__ src, const int* __restrict__ dst, int nE) {
    int t = blockIdx.x * blockDim.x + threadIdx.x;
    int e = t >> 4;
    if (e >= nE) return;
    int c = (t & 15) << 2;
    int s = __ldg(src + e);
    int d = __ldg(dst + e);
    float nm = __ldg(g_norm + e);
    float4 v = *reinterpret_cast<const float4*>(g_h + (size_t)s * HID + c);
    v.x *= nm; v.y *= nm; v.z *= nm; v.w *= nm;
    red_add_v4(g_x + (size_t)d * HID + c, v);
}

// finalize layer: x = relu(agg + h*dinv^2 + b)
__global__ void k_finalize(const float* __restrict__ b, int n) {
    int t = blockIdx.x * blockDim.x + threadIdx.x;
    int node = t >> 6, col = t & 63;
    if (node >= n) return;
    float di = g_dinv[node];
    float v = g_x[t] + g_h[t] * di * di + __ldg(b + col);
    g_x[t] = fmaxf(v, 0.f);
}

// pooling: sums + counts
__global__ void k_pool_cnt(const int* __restrict__ batch, int n) {
    int i = blockIdx.x * blockDim.x + threadIdx.x;
    if (i < n) atomicAdd(&g_cnt[batch[i]], 1);
}

__global__ void k_pool_sum(const int* __restrict__ batch, int n) {
    int t = blockIdx.x * blockDim.x + threadIdx.x;
    int node = t >> 4;
    if (node >= n) return;
    int c = (t & 15) << 2;
    int g = __ldg(batch + node);
    float4 v = *reinterpret_cast<const float4*>(g_x + (size_t)node * HID + c);
    red_add_v4(g_pool + g * HID + c, v);
}

// out = relu( (pool/cnt) @ Wfc + bfc );  grid = N_GRAPHS, block = EMB
__global__ void k_fc(const float* __restrict__ Wfc, const float* __restrict__ bfc,
                     float* __restrict__ out) {
    __shared__ float m[HID];
    int g = blockIdx.x;
    if (threadIdx.x < HID) {
        float c = fmaxf((float)g_cnt[g], 1.0f);
        m[threadIdx.x] = g_pool[g * HID + threadIdx.x] / c;
    }
    __syncthreads();
    int col = threadIdx.x;  // 0..127
    float acc = __ldg(bfc + col);
    #pragma unroll
    for (int k = 0; k < HID; k++)
        acc = fmaf(m[k], __ldg(Wfc + k * EMB + col), acc);
    out[g * EMB + col] = fmaxf(acc, 0.f);
}

// ---------------- launch ----------------
extern "C" void kernel_launch(void* const* d_in, const int* in_sizes, int n_in,
                              void* d_out, int out_size) {
    const float* x     = (const float*)d_in[0];
    const int*   ei    = (const int*)d_in[1];   // [2, E]: src row then dst row
    const int*   batch = (const int*)d_in[2];
    const float* W1 = (const float*)d_in[3];
    const float* b1 = (const float*)d_in[4];
    const float* W2 = (const float*)d_in[5];
    const float* b2 = (const float*)d_in[6];
    const float* W3 = (const float*)d_in[7];
    const float* b3 = (const float*)d_in[8];
    const float* Wfc = (const float*)d_in[9];
    const float* bfc = (const float*)d_in[10];
    float* out = (float*)d_out;

    const int n  = in_sizes[0] / F_IN;   // 50000
    const int nE = in_sizes[1] / 2;      // 800000

    const int T = 256;
    const int gN   = (n + T - 1) / T;
    const int gE   = (nE + T - 1) / T;
    const int gNC  = (n * HID + T - 1) / T;           // node*col threads
    const int gE16 = (nE * 16 + T - 1) / T;           // 16 threads / edge
    const int gN16 = (n * 16 + T - 1) / T;

    // degree + norm (shared across layers)
    k_init<<<gN, T>>>(n);
    k_count_deg<<<gE, T>>>(ei + nE, nE);
    k_dinv<<<gN, T>>>(n);
    k_norm<<<gE, T>>>(ei, ei + nE, nE);

    float* gx_ptr;
    cudaGetSymbolAddress((void**)&gx_ptr, g_x);

    // ---- layer 1 ----
    k_gemm_in6<<<gNC, T>>>(x, W1, n);
    k_zero<<<gNC, T>>>(gx_ptr, n * HID);
    k_scatter<<<gE16, T>>>(ei, ei + nE, nE);
    k_finalize<<<gNC, T>>>(b1, n);

    // ---- layer 2 ----
    k_gemm64<<<(n + 3) / 4, 256>>>(W2, n);
    k_zero<<<gNC, T>>>(gx_ptr, n * HID);
    k_scatter<<<gE16, T>>>(ei, ei + nE, nE);
    k_finalize<<<gNC, T>>>(b2, n);

    // ---- layer 3 ----
    k_gemm64<<<(n + 3) / 4, 256>>>(W3, n);
    k_zero<<<gNC, T>>>(gx_ptr, n * HID);
    k_scatter<<<gE16, T>>>(ei, ei + nE, nE);
    k_finalize<<<gNC, T>>>(b3, n);

    // ---- pool + fc ----
    k_pool_cnt<<<gN, T>>>(batch, n);
    k_pool_sum<<<gN16, T>>>(batch, n);
    k_fc<<<N_GRAPHS, EMB>>>(Wfc, bfc, out);
}

// round 3
// speedup vs baseline: 1.6181x; 1.6181x over previous
#include <cuda_runtime.h>
#include <cuda_bf16.h>
#include <cstdint>

#define N_NODES 50000
#define N_EDGES 800000
#define N_GRAPHS 64
#define F_IN 6
#define HID 64
#define EMB 128

// ---------------- scratch (static device globals; no allocation) ----------------
__device__ __align__(16) float g_h[(size_t)N_NODES * HID];   // pre-aggregation h = x@W
__device__ __align__(16) float g_x[(size_t)N_NODES * HID];   // post-aggregation activation (relu'd)
__device__ float g_ax6[(size_t)N_NODES * F_IN];              // aggregated 6-dim input
__device__ float g_dinv[N_NODES];
__device__ int   g_deg[N_NODES];
__device__ int   g_off[N_NODES];
__device__ int   g_cur[N_NODES];
__device__ int   g_bsum[256];
__device__ int   g_csrc[N_EDGES];                            // CSR: src node per slot
__device__ float g_cnorm[N_EDGES];                           // CSR: edge norm per slot
__device__ __align__(16) float g_pool[N_GRAPHS * HID];
__device__ int   g_cnt[N_GRAPHS];

__device__ __forceinline__ void red_add_v4(float* p, float4 v) {
    asm volatile("red.global.add.v4.f32 [%0], {%1,%2,%3,%4};"
                 :: "l"(p), "f"(v.x), "f"(v.y), "f"(v.z), "f"(v.w) : "memory");
}

// ---------------- setup kernels ----------------
__global__ void k_init(int n) {
    int i = blockIdx.x * blockDim.x + threadIdx.x;
    if (i < n) g_deg[i] = 0;
    if (i < N_GRAPHS * HID) g_pool[i] = 0.f;
    if (i < N_GRAPHS) g_cnt[i] = 0;
}

__global__ void k_count_deg(const int* __restrict__ dst, int nE) {
    int e = blockIdx.x * blockDim.x + threadIdx.x;
    if (e < nE) atomicAdd(&g_deg[dst[e]], 1);
}

__global__ void k_dinv(int n) {
    int i = blockIdx.x * blockDim.x + threadIdx.x;
    if (i < n) g_dinv[i] = rsqrtf((float)g_deg[i] + 1.0f);  // +1 self-loop
}

// block-level exclusive scan of g_deg -> g_off (local), block sums -> g_bsum
__global__ void k_scan1(int n) {
    __shared__ int sh[256];
    int i = blockIdx.x * 256 + threadIdx.x;
    int v = (i < n) ? g_deg[i] : 0;
    sh[threadIdx.x] = v;
    __syncthreads();
    #pragma unroll
    for (int off = 1; off < 256; off <<= 1) {
        int t = (threadIdx.x >= off) ? sh[threadIdx.x - off] : 0;
        __syncthreads();
        sh[threadIdx.x] += t;
        __syncthreads();
    }
    if (i < n) g_off[i] = sh[threadIdx.x] - v;   // exclusive within block
    if (threadIdx.x == 255) g_bsum[blockIdx.x] = sh[255];
}

// single-block exclusive scan of block sums (nb <= 256)
__global__ void k_scan2(int nb) {
    __shared__ int sh[256];
    int v = (threadIdx.x < nb) ? g_bsum[threadIdx.x] : 0;
    sh[threadIdx.x] = v;
    __syncthreads();
    #pragma unroll
    for (int off = 1; off < 256; off <<= 1) {
        int t = (threadIdx.x >= off) ? sh[threadIdx.x - off] : 0;
        __syncthreads();
        sh[threadIdx.x] += t;
        __syncthreads();
    }
    if (threadIdx.x < nb) g_bsum[threadIdx.x] = sh[threadIdx.x] - v;  // exclusive
}

__global__ void k_scan3(int n) {
    int i = blockIdx.x * 256 + threadIdx.x;
    if (i < n) {
        int o = g_off[i] + g_bsum[blockIdx.x];
        g_off[i] = o;
        g_cur[i] = o;
    }
}

// fill CSR slots: src id + precomputed norm
__global__ void k_fill(const int* __restrict__ src, const int* __restrict__ dst, int nE) {
    int e = blockIdx.x * blockDim.x + threadIdx.x;
    if (e >= nE) return;
    int s = src[e], d = dst[e];
    int pos = atomicAdd(&g_cur[d], 1);
    g_csrc[pos] = s;
    g_cnorm[pos] = g_dinv[s] * g_dinv[d];
}

// ---------------- layer kernels ----------------

// aggregate 6-dim raw input: g_ax6 = A_hat @ x   (8 threads/node, 6 active)
__global__ void k_agg6(const float* __restrict__ x, int n) {
    int t = blockIdx.x * blockDim.x + threadIdx.x;
    int node = t >> 3, c = t & 7;
    if (node >= n || c >= F_IN) return;
    float di = g_dinv[node];
    float acc = __ldg(x + (size_t)node * F_IN + c) * di * di;   // self-loop
    int p = g_off[node], e = p + g_deg[node];
    for (; p < e; p++) {
        int s = __ldg(g_csrc + p);
        float nm = __ldg(g_cnorm + p);
        acc = fmaf(__ldg(x + (size_t)s * F_IN + c), nm, acc);
    }
    g_ax6[(size_t)node * F_IN + c] = acc;
}

// g_x = relu(g_ax6 @ W1 + b1)
__global__ void k_gemm6(const float* __restrict__ W, const float* __restrict__ b, int n) {
    __shared__ float Ws[F_IN][HID];
    int tid = threadIdx.x;
    for (int i = tid; i < F_IN * HID; i += 256)       // FIX: 384 > 256, must stride
        Ws[i >> 6][i & 63] = W[i];
    __syncthreads();
    int t = blockIdx.x * blockDim.x + tid;
    int node = t >> 6, col = t & 63;
    if (node >= n) return;
    float acc = __ldg(b + col);
    #pragma unroll
    for (int k = 0; k < F_IN; k++)
        acc = fmaf(g_ax6[(size_t)node * F_IN + k], Ws[k][col], acc);
    g_x[t] = fmaxf(acc, 0.f);
}

// g_h = g_x @ W  (block: 4 nodes x 64 cols, W + x rows staged in shared)
__global__ void k_gemm64(const float* __restrict__ W, int n) {
    __shared__ float Ws[HID][HID + 1];
    __shared__ float Xs[4][HID];
    int tid = threadIdx.x;
    #pragma unroll
    for (int i = tid; i < HID * HID; i += 256)
        Ws[i >> 6][i & 63] = W[i];
    int ln = tid >> 6, col = tid & 63;
    int node = blockIdx.x * 4 + ln;
    Xs[ln][col] = (node < n) ? g_x[(size_t)node * HID + col] : 0.f;
    __syncthreads();
    if (node >= n) return;
    float acc = 0.f;
    #pragma unroll
    for (int k = 0; k < HID; k++)
        acc = fmaf(Xs[ln][k], Ws[k][col], acc);
    g_h[(size_t)node * HID + col] = acc;
}

// g_x = relu(A_hat @ g_h + b)   (16 threads/node, float4 cols, register accum)
// POOL: also reduce into g_pool (final layer) instead of only writing g_x
template <bool POOL>
__global__ void k_agg64(const float* __restrict__ b, const int* __restrict__ batch, int n) {
    int t = blockIdx.x * blockDim.x + threadIdx.x;
    int node = t >> 4;
    if (node >= n) return;
    int c = (t & 15) << 2;
    float di = g_dinv[node];
    float sl = di * di;
    float4 acc = *reinterpret_cast<const float4*>(g_h + (size_t)node * HID + c);
    acc.x *= sl; acc.y *= sl; acc.z *= sl; acc.w *= sl;
    int p = g_off[node], e = p + g_deg[node];
    for (; p < e; p++) {
        int s = __ldg(g_csrc + p);
        float nm = __ldg(g_cnorm + p);
        float4 v = *reinterpret_cast<const float4*>(g_h + (size_t)s * HID + c);
        acc.x = fmaf(v.x, nm, acc.x);
        acc.y = fmaf(v.y, nm, acc.y);
        acc.z = fmaf(v.z, nm, acc.z);
        acc.w = fmaf(v.w, nm, acc.w);
    }
    float4 bb = *reinterpret_cast<const float4*>(b + c);
    acc.x = fmaxf(acc.x + bb.x, 0.f);
    acc.y = fmaxf(acc.y + bb.y, 0.f);
    acc.z = fmaxf(acc.z + bb.z, 0.f);
    acc.w = fmaxf(acc.w + bb.w, 0.f);
    if (POOL) {
        int g = __ldg(batch + node);
        red_add_v4(g_pool + g * HID + c, acc);
    } else {
        *reinterpret_cast<float4*>(g_x + (size_t)node * HID + c) = acc;
    }
}

// ---------------- pool + fc ----------------
__global__ void k_pool_cnt(const int* __restrict__ batch, int n) {
    int i = blockIdx.x * blockDim.x + threadIdx.x;
    if (i < n) atomicAdd(&g_cnt[batch[i]], 1);
}

__global__ void k_fc(const float* __restrict__ Wfc, const float* __restrict__ bfc,
                     float* __restrict__ out) {
    __shared__ float m[HID];
    int g = blockIdx.x;
    if (threadIdx.x < HID) {
        float c = fmaxf((float)g_cnt[g], 1.0f);
        m[threadIdx.x] = g_pool[g * HID + threadIdx.x] / c;
    }
    __syncthreads();
    int col = threadIdx.x;
    float acc = __ldg(bfc + col);
    #pragma unroll
    for (int k = 0; k < HID; k++)
        acc = fmaf(m[k], __ldg(Wfc + k * EMB + col), acc);
    out[g * EMB + col] = fmaxf(acc, 0.f);
}

// ---------------- launch ----------------
extern "C" void kernel_launch(void* const* d_in, const int* in_sizes, int n_in,
                              void* d_out, int out_size) {
    const float* x     = (const float*)d_in[0];
    const int*   ei    = (const int*)d_in[1];
    const int*   batch = (const int*)d_in[2];
    const float* W1 = (const float*)d_in[3];
    const float* b1 = (const float*)d_in[4];
    const float* W2 = (const float*)d_in[5];
    const float* b2 = (const float*)d_in[6];
    const float* W3 = (const float*)d_in[7];
    const float* b3 = (const float*)d_in[8];
    const float* Wfc = (const float*)d_in[9];
    const float* bfc = (const float*)d_in[10];
    float* out = (float*)d_out;

    const int n  = in_sizes[0] / F_IN;
    const int nE = in_sizes[1] / 2;

    const int T = 256;
    const int gN   = (n + T - 1) / T;            // 196 blocks (<=256, scan-safe)
    const int gE   = (nE + T - 1) / T;
    const int gNC  = (n * HID + T - 1) / T;
    const int gN8  = (n * 8 + T - 1) / T;
    const int gN16 = (n * 16 + T - 1) / T;

    // setup: degrees, dinv, CSR
    k_init<<<gN, T>>>(n);
    k_count_deg<<<gE, T>>>(ei + nE, nE);
    k_dinv<<<gN, T>>>(n);
    k_scan1<<<gN, T>>>(n);
    k_scan2<<<1, T>>>(gN);
    k_scan3<<<gN, T>>>(n);
    k_fill<<<gE, T>>>(ei, ei + nE, nE);

    // layer 1: aggregate raw 6-dim x, then 6->64 gemm (+bias+relu)
    k_agg6<<<gN8, T>>>(x, n);
    k_gemm6<<<gNC, T>>>(W1, b1, n);

    // layer 2
    k_gemm64<<<(n + 3) / 4, T>>>(W2, n);
    k_agg64<false><<<gN16, T>>>(b2, batch, n);

    // layer 3 (aggregation fused with mean-pool reduction)
    k_gemm64<<<(n + 3) / 4, T>>>(W3, n);
    k_pool_cnt<<<gN, T>>>(batch, n);
    k_agg64<true><<<gN16, T>>>(b3, batch, n);

    // fc
    k_fc<<<N_GRAPHS, EMB>>>(Wfc, bfc, out);
}

// round 4
// speedup vs baseline: 1.8993x; 1.1738x over previous
#include <cuda_runtime.h>
#include <cuda_bf16.h>
#include <cstdint>

#define N_NODES 50000
#define N_EDGES 800000
#define N_GRAPHS 64
#define F_IN 6
#define HID 64
#define EMB 128

// ---------------- scratch (static device globals; no allocation) ----------------
__device__ __align__(16) float g_h[(size_t)N_NODES * HID];   // pre-aggregation h = x@W
__device__ __align__(16) float g_x[(size_t)N_NODES * HID];   // post-aggregation activation (relu'd)
__device__ float g_ax6[(size_t)N_NODES * F_IN];              // aggregated 6-dim input
__device__ float g_dinv[N_NODES];
__device__ int   g_deg[N_NODES];
__device__ int   g_off[N_NODES];
__device__ int   g_cur[N_NODES];
__device__ int   g_bsum[256];
__device__ __align__(8) int2 g_cedge[N_EDGES];               // CSR slot: {src, norm bits}
__device__ __align__(16) float g_pool[N_GRAPHS * HID];
__device__ int   g_cnt[N_GRAPHS];

__device__ __forceinline__ void red_add_v4(float* p, float4 v) {
    asm volatile("red.global.add.v4.f32 [%0], {%1,%2,%3,%4};"
                 :: "l"(p), "f"(v.x), "f"(v.y), "f"(v.z), "f"(v.w) : "memory");
}

// ---------------- setup kernels ----------------
__global__ void k_init(int n) {
    int i = blockIdx.x * blockDim.x + threadIdx.x;
    if (i < n) g_deg[i] = 0;
    if (i < N_GRAPHS * HID) g_pool[i] = 0.f;
    if (i < N_GRAPHS) g_cnt[i] = 0;
}

// degree histogram + graph-size histogram in one pass
__global__ void k_count(const int* __restrict__ dst, const int* __restrict__ batch,
                        int nE, int n) {
    int e = blockIdx.x * blockDim.x + threadIdx.x;
    if (e < nE) atomicAdd(&g_deg[dst[e]], 1);
    if (e < n)  atomicAdd(&g_cnt[batch[e]], 1);
}

// block-level exclusive scan of g_deg -> g_off (local), block sums -> g_bsum; also dinv
__global__ void k_scan1(int n) {
    __shared__ int sh[256];
    int i = blockIdx.x * 256 + threadIdx.x;
    int v = (i < n) ? g_deg[i] : 0;
    sh[threadIdx.x] = v;
    __syncthreads();
    #pragma unroll
    for (int off = 1; off < 256; off <<= 1) {
        int t = (threadIdx.x >= off) ? sh[threadIdx.x - off] : 0;
        __syncthreads();
        sh[threadIdx.x] += t;
        __syncthreads();
    }
    if (i < n) {
        g_off[i] = sh[threadIdx.x] - v;                  // exclusive within block
        g_dinv[i] = rsqrtf((float)v + 1.0f);             // +1 self-loop
    }
    if (threadIdx.x == 255) g_bsum[blockIdx.x] = sh[255];
}

// single-block exclusive scan of block sums (nb <= 256)
__global__ void k_scan2(int nb) {
    __shared__ int sh[256];
    int v = (threadIdx.x < nb) ? g_bsum[threadIdx.x] : 0;
    sh[threadIdx.x] = v;
    __syncthreads();
    #pragma unroll
    for (int off = 1; off < 256; off <<= 1) {
        int t = (threadIdx.x >= off) ? sh[threadIdx.x - off] : 0;
        __syncthreads();
        sh[threadIdx.x] += t;
        __syncthreads();
    }
    if (threadIdx.x < nb) g_bsum[threadIdx.x] = sh[threadIdx.x] - v;
}

__global__ void k_scan3(int n) {
    int i = blockIdx.x * 256 + threadIdx.x;
    if (i < n) {
        int o = g_off[i] + g_bsum[blockIdx.x];
        g_off[i] = o;
        g_cur[i] = o;
    }
}

// fill CSR slots: packed {src, norm}
__global__ void k_fill(const int* __restrict__ src, const int* __restrict__ dst, int nE) {
    int e = blockIdx.x * blockDim.x + threadIdx.x;
    if (e >= nE) return;
    int s = src[e], d = dst[e];
    int pos = atomicAdd(&g_cur[d], 1);
    float nm = g_dinv[s] * g_dinv[d];
    g_cedge[pos] = make_int2(s, __float_as_int(nm));
}

// ---------------- layer kernels ----------------

// aggregate 6-dim raw input: g_ax6 = A_hat @ x   (8 threads/node, 6 active)
__global__ void k_agg6(const float* __restrict__ x, int n) {
    int t = blockIdx.x * blockDim.x + threadIdx.x;
    int node = t >> 3, c = t & 7;
    if (node >= n || c >= F_IN) return;
    float di = g_dinv[node];
    float acc = __ldg(x + (size_t)node * F_IN + c) * di * di;   // self-loop
    int p = g_off[node], e = p + g_deg[node];
    for (; p < e; p++) {
        int2 ed = __ldg(&g_cedge[p]);
        acc = fmaf(__ldg(x + (size_t)ed.x * F_IN + c), __int_as_float(ed.y), acc);
    }
    g_ax6[(size_t)node * F_IN + c] = acc;
}

// g_x = relu(g_ax6 @ W1 + b1)
__global__ void k_gemm6(const float* __restrict__ W, const float* __restrict__ b, int n) {
    __shared__ float Ws[F_IN][HID];
    int tid = threadIdx.x;
    for (int i = tid; i < F_IN * HID; i += 256)
        Ws[i >> 6][i & 63] = W[i];
    __syncthreads();
    int t = blockIdx.x * blockDim.x + tid;
    int node = t >> 6, col = t & 63;
    if (node >= n) return;
    float acc = __ldg(b + col);
    #pragma unroll
    for (int k = 0; k < F_IN; k++)
        acc = fmaf(g_ax6[(size_t)node * F_IN + k], Ws[k][col], acc);
    g_x[t] = fmaxf(acc, 0.f);
}

// g_h = g_x @ W   (register-tiled: 1 thread = 1 node x 4 cols; 16 nodes/block)
__global__ void k_gemm64(const float* __restrict__ W, int n) {
    __shared__ float4 Ws[HID][HID / 4];       // [k][colgroup], 16KB
    __shared__ float Xs[16][HID + 4];         // +4 pad: keeps 16B align, shifts banks
    int tid = threadIdx.x;                    // 256
    const float4* W4 = reinterpret_cast<const float4*>(W);
    #pragma unroll
    for (int i = tid; i < HID * HID / 4; i += 256)
        Ws[i >> 4][i & 15] = W4[i];
    int ln = tid >> 4;        // node lane 0..15
    int cg = tid & 15;        // col group 0..15
    int node = blockIdx.x * 16 + ln;
    float4 xin = (node < n)
        ? *reinterpret_cast<const float4*>(g_x + (size_t)node * HID + cg * 4)
        : make_float4(0.f, 0.f, 0.f, 0.f);
    *reinterpret_cast<float4*>(&Xs[ln][cg * 4]) = xin;
    __syncthreads();
    if (node >= n) return;
    float4 acc = make_float4(0.f, 0.f, 0.f, 0.f);
    #pragma unroll
    for (int k = 0; k < HID; k++) {
        float xv = Xs[ln][k];
        float4 w = Ws[k][cg];
        acc.x = fmaf(xv, w.x, acc.x);
        acc.y = fmaf(xv, w.y, acc.y);
        acc.z = fmaf(xv, w.z, acc.z);
        acc.w = fmaf(xv, w.w, acc.w);
    }
    *reinterpret_cast<float4*>(g_h + (size_t)node * HID + cg * 4) = acc;
}

// g_x = relu(A_hat @ g_h + b)   (16 threads/node, float4 cols, 2x unrolled gather)
template <bool POOL>
__global__ void k_agg64(const float* __restrict__ b, const int* __restrict__ batch, int n) {
    int t = blockIdx.x * blockDim.x + threadIdx.x;
    int node = t >> 4;
    if (node >= n) return;
    int c = (t & 15) << 2;
    float di = g_dinv[node];
    float sl = di * di;
    float4 acc = *reinterpret_cast<const float4*>(g_h + (size_t)node * HID + c);
    acc.x *= sl; acc.y *= sl; acc.z *= sl; acc.w *= sl;
    int p = g_off[node], e = p + g_deg[node];
    for (; p + 1 < e; p += 2) {
        int2 e0 = __ldg(&g_cedge[p]);
        int2 e1 = __ldg(&g_cedge[p + 1]);
        float4 v0 = *reinterpret_cast<const float4*>(g_h + (size_t)e0.x * HID + c);
        float4 v1 = *reinterpret_cast<const float4*>(g_h + (size_t)e1.x * HID + c);
        float n0 = __int_as_float(e0.y), n1 = __int_as_float(e1.y);
        acc.x = fmaf(v0.x, n0, acc.x);
        acc.y = fmaf(v0.y, n0, acc.y);
        acc.z = fmaf(v0.z, n0, acc.z);
        acc.w = fmaf(v0.w, n0, acc.w);
        acc.x = fmaf(v1.x, n1, acc.x);
        acc.y = fmaf(v1.y, n1, acc.y);
        acc.z = fmaf(v1.z, n1, acc.z);
        acc.w = fmaf(v1.w, n1, acc.w);
    }
    if (p < e) {
        int2 e0 = __ldg(&g_cedge[p]);
        float4 v0 = *reinterpret_cast<const float4*>(g_h + (size_t)e0.x * HID + c);
        float n0 = __int_as_float(e0.y);
        acc.x = fmaf(v0.x, n0, acc.x);
        acc.y = fmaf(v0.y, n0, acc.y);
        acc.z = fmaf(v0.z, n0, acc.z);
        acc.w = fmaf(v0.w, n0, acc.w);
    }
    float4 bb = *reinterpret_cast<const float4*>(b + c);
    acc.x = fmaxf(acc.x + bb.x, 0.f);
    acc.y = fmaxf(acc.y + bb.y, 0.f);
    acc.z = fmaxf(acc.z + bb.z, 0.f);
    acc.w = fmaxf(acc.w + bb.w, 0.f);
    if (POOL) {
        int g = __ldg(batch + node);
        red_add_v4(g_pool + g * HID + c, acc);
    } else {
        *reinterpret_cast<float4*>(g_x + (size_t)node * HID + c) = acc;
    }
}

// ---------------- fc ----------------
__global__ void k_fc(const float* __restrict__ Wfc, const float* __restrict__ bfc,
                     float* __restrict__ out) {
    __shared__ float m[HID];
    int g = blockIdx.x;
    if (threadIdx.x < HID) {
        float c = fmaxf((float)g_cnt[g], 1.0f);
        m[threadIdx.x] = g_pool[g * HID + threadIdx.x] / c;
    }
    __syncthreads();
    int col = threadIdx.x;
    float acc = __ldg(bfc + col);
    #pragma unroll
    for (int k = 0; k < HID; k++)
        acc = fmaf(m[k], __ldg(Wfc + k * EMB + col), acc);
    out[g * EMB + col] = fmaxf(acc, 0.f);
}

// ---------------- launch ----------------
extern "C" void kernel_launch(void* const* d_in, const int* in_sizes, int n_in,
                              void* d_out, int out_size) {
    const float* x     = (const float*)d_in[0];
    const int*   ei    = (const int*)d_in[1];
    const int*   batch = (const int*)d_in[2];
    const float* W1 = (const float*)d_in[3];
    const float* b1 = (const float*)d_in[4];
    const float* W2 = (const float*)d_in[5];
    const float* b2 = (const float*)d_in[6];
    const float* W3 = (const float*)d_in[7];
    const float* b3 = (const float*)d_in[8];
    const float* Wfc = (const float*)d_in[9];
    const float* bfc = (const float*)d_in[10];
    float* out = (float*)d_out;

    const int n  = in_sizes[0] / F_IN;
    const int nE = in_sizes[1] / 2;

    const int T = 256;
    const int gN   = (n + T - 1) / T;            // 196 blocks (<=256, scan-safe)
    const int gE   = (nE + T - 1) / T;
    const int gNC  = (n * HID + T - 1) / T;
    const int gN8  = (n * 8 + T - 1) / T;
    const int gN16 = (n * 16 + T - 1) / T;

    // setup: degrees+counts, dinv, CSR
    k_init<<<gN, T>>>(n);
    k_count<<<gE, T>>>(ei + nE, batch, nE, n);
    k_scan1<<<gN, T>>>(n);
    k_scan2<<<1, T>>>(gN);
    k_scan3<<<gN, T>>>(n);
    k_fill<<<gE, T>>>(ei, ei + nE, nE);

    // layer 1: aggregate raw 6-dim x, then 6->64 gemm (+bias+relu)
    k_agg6<<<gN8, T>>>(x, n);
    k_gemm6<<<gNC, T>>>(W1, b1, n);

    // layer 2
    k_gemm64<<<(n + 15) / 16, T>>>(W2, n);
    k_agg64<false><<<gN16, T>>>(b2, batch, n);

    // layer 3 (aggregation fused with mean-pool reduction)
    k_gemm64<<<(n + 15) / 16, T>>>(W3, n);
    k_agg64<true><<<gN16, T>>>(b3, batch, n);

    // fc
    k_fc<<<N_GRAPHS, EMB>>>(Wfc, bfc, out);
}